// round 14
// baseline (speedup 1.0000x reference)
#include <cuda_runtime.h>
#include <cuda_fp16.h>
#include <stdint.h>

// HMMA fp16 2-pass split-precision flash attention, sm_103 base ISA.
// bs=4, h=16 (bs_h=64), S=2048, d=64. CTA = 128 q-rows, 8 warps x 16 rows.
// One-shot prepass converts Q(1/8)->fp16, K,V->fp16 hi+lo in __device__ bufs;
// hot loop streams tiles via double-buffered cp.async (no LDG/cvt/STS in loop).
// GEMM1: S = QF·(Khi+Klo)^T ; GEMM2: O += f16(P)·(Vhi+Vlo).
// Softmax: p = ex2(S*log2e + C), pad/causal/shift folded into C; masked -> 0.

#define ELEMS 8388608ull          // 64*2048*64 halves per tensor

__device__ __align__(16) __half gQf [ELEMS];
__device__ __align__(16) __half gKhi[ELEMS];
__device__ __align__(16) __half gKlo[ELEMS];
__device__ __align__(16) __half gVhi[ELEMS];
__device__ __align__(16) __half gVlo[ELEMS];

// smem layout (bytes). Rows are 128B (64 halves), XOR-swizzled chunks.
#define OFF_MADD 0                // float[2][64] double-buffered (C constants)
#define OFF_TRAP 512              // int[128]
#define OFF_FLAG 1024             // int
#define OFF_QF   2048             // [128][64] f16 swizzled
#define OFF_KV   (OFF_QF + 16384) // 2 stages x {Khi,Klo,Vhi,Vlo} x 8KB
#define STG      32768
#define KV_KHI 0
#define KV_KLO 8192
#define KV_VHI 16384
#define KV_VLO 24576
#define SMEM_TOTAL (OFF_KV + 2*STG)   // 84 KB -> 2 CTAs/SM

#define L2E   1.4426950408889634f
#define SHC   (-11.541560327111707f)   // -8*log2e
#define NEGC  (-1.4426950e10f)         // huge negative -> ex2 == exact 0

// ---------------------------------------------------------------- helpers
__device__ __forceinline__ uint32_t s2u(const void* p){
    uint32_t a;
    asm("{ .reg .u64 t; cvta.to.shared.u64 t, %1; cvt.u32.u64 %0, t; }"
        : "=r"(a) : "l"(p));
    return a;
}
__device__ __forceinline__ void cpa16(uint32_t dst, const void* src){
    asm volatile("cp.async.cg.shared.global [%0], [%1], 16;"
                 :: "r"(dst), "l"(src) : "memory");
}
#define CPA_COMMIT() asm volatile("cp.async.commit_group;" ::: "memory")
#define CPA_WAIT1()  asm volatile("cp.async.wait_group 1;" ::: "memory")
#define CPA_WAIT0()  asm volatile("cp.async.wait_group 0;" ::: "memory")

__device__ __forceinline__ void ldsm4(uint32_t a, uint32_t* r){
    asm volatile("ldmatrix.sync.aligned.m8n8.x4.shared.b16 {%0,%1,%2,%3}, [%4];"
        : "=r"(r[0]), "=r"(r[1]), "=r"(r[2]), "=r"(r[3]) : "r"(a));
}
__device__ __forceinline__ void ldsm4t(uint32_t a, uint32_t* r){
    asm volatile("ldmatrix.sync.aligned.m8n8.x4.trans.shared.b16 {%0,%1,%2,%3}, [%4];"
        : "=r"(r[0]), "=r"(r[1]), "=r"(r[2]), "=r"(r[3]) : "r"(a));
}
__device__ __forceinline__ void mma16816(float* c, const uint32_t* a,
                                         uint32_t b0, uint32_t b1){
    asm volatile("mma.sync.aligned.m16n8k16.row.col.f32.f16.f16.f32 "
        "{%0,%1,%2,%3},{%4,%5,%6,%7},{%8,%9},{%0,%1,%2,%3};"
        : "+f"(c[0]), "+f"(c[1]), "+f"(c[2]), "+f"(c[3])
        : "r"(a[0]), "r"(a[1]), "r"(a[2]), "r"(a[3]), "r"(b0), "r"(b1));
}
__device__ __forceinline__ float ex2f(float t){
    float p;
    asm("ex2.approx.f32 %0, %1;" : "=f"(p) : "f"(t));
    return p;
}
__device__ __forceinline__ void splitH2(float a, float b, uint32_t& hw, uint32_t& lw){
    __half2 h = __floats2half2_rn(a, b);
    float2 f = __half22float2(h);
    __half2 l = __floats2half2_rn(a - f.x, b - f.y);
    hw = *(uint32_t*)&h;
    lw = *(uint32_t*)&l;
}
__device__ __forceinline__ uint32_t packH2(float a, float b){
    __half2 h = __floats2half2_rn(a, b);
    return *(uint32_t*)&h;
}

// -------------------------------------------------------------- pre-pass
__global__ void __launch_bounds__(256)
prepass(const float* __restrict__ Q, const float* __restrict__ K,
        const float* __restrict__ V)
{
    size_t id = (size_t)blockIdx.x * 256 + threadIdx.x;   // 0..6291455
    size_t t  = id >> 21;                                  // 0=Q 1=K 2=V
    size_t p  = id & 2097151;                              // float4 index
    const float4* src = (const float4*)(t == 0 ? Q : (t == 1 ? K : V));
    float4 v = src[p];
    if (t == 0){
        uint32_t q0 = packH2(v.x * 0.125f, v.y * 0.125f);
        uint32_t q1 = packH2(v.z * 0.125f, v.w * 0.125f);
        ((uint2*)gQf)[p] = make_uint2(q0, q1);
    } else {
        uint32_t h0,l0,h1,l1;
        splitH2(v.x, v.y, h0, l0);
        splitH2(v.z, v.w, h1, l1);
        uint2* hi = (uint2*)(t == 1 ? gKhi : gVhi);
        uint2* lo = (uint2*)(t == 1 ? gKlo : gVlo);
        hi[p] = make_uint2(h0, h1);
        lo[p] = make_uint2(l0, l1);
    }
}

// ------------------------------------------------------------------- main
__global__ void __launch_bounds__(256, 2)
attn_mma(const float* __restrict__ Vg, const int* __restrict__ maskg,
         float* __restrict__ Og)
{
    extern __shared__ char SM[];
    const uint32_t sb = s2u(SM);
    const int tid  = threadIdx.x;
    const int lane = tid & 31;
    const int w    = tid >> 5;                    // warp owns rows 16w..16w+15
    const int bh   = blockIdx.y;
    const int bx   = blockIdx.x;
    const int qb   = (bx == 0) ? 0 : (16 - bx);   // trap-capable qb=0 first
    const int batch = bh & 3;

    if (tid == 0) *(int*)(SM + OFF_FLAG) = 0;

    const size_t headB = (size_t)bh * 2048 * 128;   // byte offset into f16 bufs
    float* madd = (float*)(SM + OFF_MADD);
    const int nkt = 2 * qb + 2;

    // cp.async per-thread coords: chunk c -> row c>>3, ch c&7 (16B units)
    // ---- prologue: Q tile (4 chunks/thread) + KV tile 0 (8 chunks/thread) ----
    {
        const char* qsrc = (const char*)gQf + headB + (size_t)qb * 128 * 128;
        #pragma unroll
        for (int it = 0; it < 4; ++it){
            int c = tid + 256 * it, row = c >> 3, ch = c & 7;
            uint32_t off = (uint32_t)(row * 128 + ((ch ^ (row & 7)) << 4));
            cpa16(sb + OFF_QF + off, qsrc + row * 128 + ch * 16);
        }
        #pragma unroll
        for (int it = 0; it < 2; ++it){
            int c = tid + 256 * it, row = c >> 3, ch = c & 7;
            uint32_t off = (uint32_t)(row * 128 + ((ch ^ (row & 7)) << 4));
            size_t s = headB + row * 128 + ch * 16;
            cpa16(sb + OFF_KV + KV_KHI + off, (const char*)gKhi + s);
            cpa16(sb + OFF_KV + KV_KLO + off, (const char*)gKlo + s);
            cpa16(sb + OFF_KV + KV_VHI + off, (const char*)gVhi + s);
            cpa16(sb + OFF_KV + KV_VLO + off, (const char*)gVlo + s);
        }
        if (tid < 64)
            madd[tid] = maskg[batch * 2048 + tid] ? SHC : NEGC;
        CPA_COMMIT();
    }

    float O[8][4];
    float Lrow[2] = {0.f, 0.f};
    #pragma unroll
    for (int n = 0; n < 8; ++n)
        #pragma unroll
        for (int e = 0; e < 4; ++e) O[n][e] = 0.f;

    const int lr16 = lane & 15;
    const int aCh  = lane >> 4;                    // A chunk parity
    const int bRow = (lane & 7) + ((lane >> 4) << 3);
    const int bCh  = (lane >> 3) & 1;              // B(K) chunk parity
    const int vRow = (lane & 7) + (((lane >> 3) & 1) << 3);
    const int vCh  = lane >> 4;                    // B(V) chunk parity
    const int r01  = qb * 128 + 16 * w + (lane >> 2);
    const int r23  = r01 + 8;

    for (int j = 0; j < nkt; ++j){
        const int st = j & 1;

        // ---- issue tile j+1 into stage st^1; then wait for stage st ----
        if (j + 1 < nkt){
            const uint32_t kvn = sb + OFF_KV + (uint32_t)(st ^ 1) * STG;
            const size_t tB = headB + (size_t)(j + 1) * 8192;
            #pragma unroll
            for (int it = 0; it < 2; ++it){
                int c = tid + 256 * it, row = c >> 3, ch = c & 7;
                uint32_t off = (uint32_t)(row * 128 + ((ch ^ (row & 7)) << 4));
                size_t s = tB + row * 128 + ch * 16;
                cpa16(kvn + KV_KHI + off, (const char*)gKhi + s);
                cpa16(kvn + KV_KLO + off, (const char*)gKlo + s);
                cpa16(kvn + KV_VHI + off, (const char*)gVhi + s);
                cpa16(kvn + KV_VLO + off, (const char*)gVlo + s);
            }
            if (tid < 64)
                madd[(st ^ 1) * 64 + tid] =
                    maskg[batch * 2048 + (j + 1) * 64 + tid] ? SHC : NEGC;
            CPA_COMMIT();
            CPA_WAIT1();
        } else {
            CPA_WAIT0();
        }
        __syncthreads();   // stage st (and Q on j=0) visible CTA-wide

        const uint32_t kvb = sb + OFF_KV + (uint32_t)st * STG;

        // ---- GEMM1: S = QF·Khi^T + QF·Klo^T ----
        float S[8][4];
        #pragma unroll
        for (int n = 0; n < 8; ++n)
            #pragma unroll
            for (int e = 0; e < 4; ++e) S[n][e] = 0.f;

        #pragma unroll 1
        for (int kt = 0; kt < 4; ++kt){
            uint32_t aF[4];
            {
                int row = 16 * w + lr16, ch = kt * 2 + aCh;
                ldsm4(sb + OFF_QF
                      + (uint32_t)(row * 128 + ((ch ^ (row & 7)) << 4)), aF);
            }
            #pragma unroll
            for (int u = 0; u < 4; ++u){
                uint32_t bH[4], bL[4];
                int row = 16 * u + bRow, ch = kt * 2 + bCh;
                uint32_t ad = kvb + (uint32_t)(row * 128 + ((ch ^ (row & 7)) << 4));
                ldsm4(ad + KV_KHI, bH);
                ldsm4(ad + KV_KLO, bL);
                mma16816(S[2*u],   aF, bH[0], bH[1]);
                mma16816(S[2*u],   aF, bL[0], bL[1]);
                mma16816(S[2*u+1], aF, bH[2], bH[3]);
                mma16816(S[2*u+1], aF, bL[2], bL[3]);
            }
        }

        // ---- softmax: p = ex2(S*log2e + C); masked -> exact 0 ----
        const float* mAddp = madd + st * 64;
        {
            float rs0 = 0.f, rs1 = 0.f;
            #pragma unroll
            for (int n = 0; n < 8; ++n){
                int c0 = n * 8 + 2 * (lane & 3);
                int kg = j * 64 + c0;
                float pad0 = mAddp[c0], pad1 = mAddp[c0 + 1];
                float p0 = ex2f(fmaf(S[n][0], L2E, (kg     > r01) ? NEGC : pad0));
                float p1 = ex2f(fmaf(S[n][1], L2E, (kg + 1 > r01) ? NEGC : pad1));
                float p2 = ex2f(fmaf(S[n][2], L2E, (kg     > r23) ? NEGC : pad0));
                float p3 = ex2f(fmaf(S[n][3], L2E, (kg + 1 > r23) ? NEGC : pad1));
                S[n][0] = p0; S[n][1] = p1;
                S[n][2] = p2; S[n][3] = p3;
                rs0 += p0 + p1;
                rs1 += p2 + p3;
            }
            rs0 += __shfl_xor_sync(0xffffffffu, rs0, 1);
            rs0 += __shfl_xor_sync(0xffffffffu, rs0, 2);
            rs1 += __shfl_xor_sync(0xffffffffu, rs1, 1);
            rs1 += __shfl_xor_sync(0xffffffffu, rs1, 2);
            Lrow[0] += rs0;
            Lrow[1] += rs1;
        }

        // ---- GEMM2: O += f16(P)·Vhi + f16(P)·Vlo ----
        #pragma unroll 1
        for (int kt2 = 0; kt2 < 4; ++kt2){
            uint32_t aF[4];
            aF[0] = packH2(S[2*kt2  ][0], S[2*kt2  ][1]);
            aF[1] = packH2(S[2*kt2  ][2], S[2*kt2  ][3]);
            aF[2] = packH2(S[2*kt2+1][0], S[2*kt2+1][1]);
            aF[3] = packH2(S[2*kt2+1][2], S[2*kt2+1][3]);
            #pragma unroll
            for (int du = 0; du < 4; ++du){
                uint32_t bVh[4], bVl[4];
                int row = 16 * kt2 + vRow, ch = du * 2 + vCh;
                uint32_t ad = kvb + (uint32_t)(row * 128 + ((ch ^ (row & 7)) << 4));
                ldsm4t(ad + KV_VHI, bVh);
                ldsm4t(ad + KV_VLO, bVl);
                mma16816(O[2*du],   aF, bVh[0], bVh[1]);
                mma16816(O[2*du],   aF, bVl[0], bVl[1]);
                mma16816(O[2*du+1], aF, bVh[2], bVh[3]);
                mma16816(O[2*du+1], aF, bVl[2], bVl[3]);
            }
        }
        __syncthreads();   // stage st fully consumed before next-iter refill
    }

    // ---- epilogue: trap flags, normalize, store ----
    int* trapA = (int*)(SM + OFF_TRAP);
    #pragma unroll
    for (int hf = 0; hf < 2; ++hf){
        float l = Lrow[hf];
        if ((lane & 3) == 0){
            int r = 16*w + (lane >> 2) + 8*hf;
            int t = (l == 0.f) ? 1 : 0;
            trapA[r] = t;
            if (t) *(volatile int*)(SM + OFF_FLAG) = 1;
        }
    }

    float* Op = Og + ((size_t)bh * 2048 + (size_t)qb * 128) * 64;
    {
        float inv0 = 1.f / Lrow[0];
        float inv1 = 1.f / Lrow[1];
        int rr0 = 16*w + (lane >> 2);
        int rr1 = rr0 + 8;
        #pragma unroll
        for (int dt = 0; dt < 8; ++dt){
            int c = dt * 8 + 2 * (lane & 3);
            *(float2*)(Op + (size_t)rr0 * 64 + c) =
                make_float2(O[dt][0] * inv0, O[dt][1] * inv0);
            *(float2*)(Op + (size_t)rr1 * 64 + c) =
                make_float2(O[dt][2] * inv1, O[dt][3] * inv1);
        }
    }

    // ---- trap rows: reference collapses to UNIFORM attention over
    //      {k <= q} U {k > q unmasked} (fp32 absorbs s into -1e10 exactly) ----
    __syncthreads();
    if (*(volatile int*)(SM + OFF_FLAG)){
        for (int r = 0; r < 128; ++r){
            if (!trapA[r]) continue;
            int qr = qb * 128 + r;
            if (tid < 64){
                const float* Vb = Vg + (size_t)bh * 2048 * 64;
                const int*   mb = maskg + batch * 2048;
                float acc = 0.f; int cnt = 0;
                for (int k = 0; k < 2048; ++k){
                    bool ok = (k <= qr) || (mb[k] != 0);
                    if (ok){ acc += Vb[(size_t)k * 64 + tid]; cnt++; }
                }
                Og[((size_t)bh * 2048 + qr) * 64 + tid] = acc / (float)cnt;
            }
        }
    }
}

extern "C" void kernel_launch(void* const* d_in, const int* in_sizes, int n_in,
                              void* d_out, int out_size)
{
    const float* Q    = (const float*)d_in[0];
    const float* K    = (const float*)d_in[1];
    const float* V    = (const float*)d_in[2];
    const int*   mask = (const int*)d_in[3];
    float* O = (float*)d_out;

    prepass<<<24576, 256>>>(Q, K, V);

    cudaFuncSetAttribute(attn_mma, cudaFuncAttributeMaxDynamicSharedMemorySize,
                         SMEM_TOTAL);
    dim3 grid(16, 64);
    attn_mma<<<grid, 256, SMEM_TOTAL>>>(V, mask, O);
}

// round 15
// speedup vs baseline: 1.2845x; 1.2845x over previous
#include <cuda_runtime.h>
#include <cuda_fp16.h>
#include <stdint.h>

// HMMA fp16 single-pass flash attention, sm_103 base ISA.
// bs=4, h=16 (bs_h=64), S=2048, d=64. CTA = 128 q-rows, 8 warps x 16 rows.
// R13 structure (in-loop convert, 2 barriers/tile) slimmed: single fp16 pass
// for both GEMMs (error budget ~4e-4 < 1e-3), Q fragments hoisted to regs.
// Softmax: p = ex2(S*log2e + C), pad/causal/shift folded into C; masked -> 0.

#define QSTRIDE 144               // f16 tile row pitch bytes (72 halves)

#define OFF_MADD 0                // float[64]: C per key col
#define OFF_TRAP 256              // int[128]
#define OFF_FLAG 768              // int
#define OFF_QF   1024             // [128][72] f16
#define OFF_KF   (OFF_QF + 128*QSTRIDE)    // [64][72]
#define OFF_VF   (OFF_KF + 64*QSTRIDE)     // [key][dim]
#define SMEM_TOTAL (OFF_VF + 64*QSTRIDE)   // 37888 B -> 2 CTAs/SM (reg-capped)

#define L2E   1.4426950408889634f
#define SHC   (-11.541560327111707f)   // -8*log2e
#define NEGC  (-1.4426950e10f)         // huge negative -> ex2 == exact 0

// ---------------------------------------------------------------- helpers
__device__ __forceinline__ uint32_t s2u(const void* p){
    uint32_t a;
    asm("{ .reg .u64 t; cvta.to.shared.u64 t, %1; cvt.u32.u64 %0, t; }"
        : "=r"(a) : "l"(p));
    return a;
}
__device__ __forceinline__ void ldsm4(uint32_t a, uint32_t* r){
    asm volatile("ldmatrix.sync.aligned.m8n8.x4.shared.b16 {%0,%1,%2,%3}, [%4];"
        : "=r"(r[0]), "=r"(r[1]), "=r"(r[2]), "=r"(r[3]) : "r"(a));
}
__device__ __forceinline__ void ldsm4t(uint32_t a, uint32_t* r){
    asm volatile("ldmatrix.sync.aligned.m8n8.x4.trans.shared.b16 {%0,%1,%2,%3}, [%4];"
        : "=r"(r[0]), "=r"(r[1]), "=r"(r[2]), "=r"(r[3]) : "r"(a));
}
__device__ __forceinline__ void mma16816(float* c, const uint32_t* a,
                                         uint32_t b0, uint32_t b1){
    asm volatile("mma.sync.aligned.m16n8k16.row.col.f32.f16.f16.f32 "
        "{%0,%1,%2,%3},{%4,%5,%6,%7},{%8,%9},{%0,%1,%2,%3};"
        : "+f"(c[0]), "+f"(c[1]), "+f"(c[2]), "+f"(c[3])
        : "r"(a[0]), "r"(a[1]), "r"(a[2]), "r"(a[3]), "r"(b0), "r"(b1));
}
__device__ __forceinline__ float ex2f(float t){
    float p;
    asm("ex2.approx.f32 %0, %1;" : "=f"(p) : "f"(t));
    return p;
}
__device__ __forceinline__ uint32_t packH2(float a, float b){
    __half2 h = __floats2half2_rn(a, b);
    return *(uint32_t*)&h;
}

// ------------------------------------------------------------------- kernel
__global__ void __launch_bounds__(256, 2)
attn_mma(const float* __restrict__ Qg, const float* __restrict__ Kg,
         const float* __restrict__ Vg, const int* __restrict__ maskg,
         float* __restrict__ Og)
{
    extern __shared__ char SM[];
    const uint32_t sb = s2u(SM);
    const int tid  = threadIdx.x;
    const int lane = tid & 31;
    const int w    = tid >> 5;                    // warp owns rows 16w..16w+15
    const int bh   = blockIdx.y;
    const int bx   = blockIdx.x;
    const int qb   = (bx == 0) ? 0 : (16 - bx);   // trap-capable qb=0 first
    const int batch = bh & 3;

    if (tid == 0) *(int*)(SM + OFF_FLAG) = 0;

    // ---- convert Q tile (pre-scaled by 1/8) -> fp16 smem ----
    const float* Qp = Qg + ((size_t)bh * 2048 + (size_t)qb * 128) * 64;
    for (int i = tid; i < 2048; i += 256){
        int r = i >> 4, c4 = (i & 15) << 2;
        float4 v = *(const float4*)(Qp + r * 64 + c4);
        uint32_t q0 = packH2(v.x * 0.125f, v.y * 0.125f);
        uint32_t q1 = packH2(v.z * 0.125f, v.w * 0.125f);
        *(uint2*)(SM + OFF_QF + (uint32_t)(r * QSTRIDE + c4 * 2)) = make_uint2(q0, q1);
    }
    __syncthreads();

    // ---- hoist Q fragments into registers (loop-invariant) ----
    const int lr16 = lane & 15;
    const int aCh  = (lane >> 4) << 4;
    uint32_t aF[4][4];
    #pragma unroll
    for (int kt = 0; kt < 4; ++kt)
        ldsm4(sb + OFF_QF + (uint32_t)((16*w + lr16) * QSTRIDE + kt*32 + aCh),
              aF[kt]);

    float O[8][4];
    float Lrow[2] = {0.f, 0.f};
    #pragma unroll
    for (int n = 0; n < 8; ++n)
        #pragma unroll
        for (int e = 0; e < 4; ++e) O[n][e] = 0.f;

    const int bRow = (lane & 7) + ((lane >> 4) << 3);
    const int bCh  = ((lane >> 3) & 1) << 4;
    const int vRow = (lane & 7) + (((lane >> 3) & 1) << 3);
    const int vCh  = (lane >> 4) << 4;
    const int r01  = qb * 128 + 16 * w + (lane >> 2);
    const int r23  = r01 + 8;

    const int nkt = 2 * qb + 2;
    for (int j = 0; j < nkt; ++j){
        __syncthreads();   // previous tile's K/V smem reads done
        // ---- convert K,V tiles -> fp16 (single precision pass) ----
        const float* Kp = Kg + ((size_t)bh * 2048 + (size_t)j * 64) * 64;
        const float* Vp = Vg + ((size_t)bh * 2048 + (size_t)j * 64) * 64;
        for (int i = tid; i < 1024; i += 256){
            int r = i >> 4, c4 = (i & 15) << 2;
            uint32_t off = (uint32_t)(r * QSTRIDE + c4 * 2);
            float4 v = *(const float4*)(Kp + r * 64 + c4);
            *(uint2*)(SM + OFF_KF + off) =
                make_uint2(packH2(v.x, v.y), packH2(v.z, v.w));
            v = *(const float4*)(Vp + r * 64 + c4);
            *(uint2*)(SM + OFF_VF + off) =
                make_uint2(packH2(v.x, v.y), packH2(v.z, v.w));
        }
        if (tid < 64)
            ((float*)(SM + OFF_MADD))[tid] =
                maskg[batch * 2048 + j * 64 + tid] ? SHC : NEGC;
        __syncthreads();

        // ---- GEMM1: S = QF·KF^T ----
        float S[8][4];
        #pragma unroll
        for (int n = 0; n < 8; ++n)
            #pragma unroll
            for (int e = 0; e < 4; ++e) S[n][e] = 0.f;

        #pragma unroll 1
        for (int kt = 0; kt < 4; ++kt){
            #pragma unroll
            for (int u = 0; u < 4; ++u){
                uint32_t bF[4];
                ldsm4(sb + OFF_KF
                      + (uint32_t)((16*u + bRow) * QSTRIDE + kt*32 + bCh), bF);
                mma16816(S[2*u],   aF[kt], bF[0], bF[1]);
                mma16816(S[2*u+1], aF[kt], bF[2], bF[3]);
            }
        }

        // ---- softmax: p = ex2(S*log2e + C); masked -> exact 0 ----
        const float* mAddp = (const float*)(SM + OFF_MADD);
        {
            float rs0 = 0.f, rs1 = 0.f;
            #pragma unroll
            for (int n = 0; n < 8; ++n){
                int c0 = n * 8 + 2 * (lane & 3);
                int kg = j * 64 + c0;
                float pad0 = mAddp[c0], pad1 = mAddp[c0 + 1];
                float p0 = ex2f(fmaf(S[n][0], L2E, (kg     > r01) ? NEGC : pad0));
                float p1 = ex2f(fmaf(S[n][1], L2E, (kg + 1 > r01) ? NEGC : pad1));
                float p2 = ex2f(fmaf(S[n][2], L2E, (kg     > r23) ? NEGC : pad0));
                float p3 = ex2f(fmaf(S[n][3], L2E, (kg + 1 > r23) ? NEGC : pad1));
                S[n][0] = p0; S[n][1] = p1;
                S[n][2] = p2; S[n][3] = p3;
                rs0 += p0 + p1;
                rs1 += p2 + p3;
            }
            rs0 += __shfl_xor_sync(0xffffffffu, rs0, 1);
            rs0 += __shfl_xor_sync(0xffffffffu, rs0, 2);
            rs1 += __shfl_xor_sync(0xffffffffu, rs1, 1);
            rs1 += __shfl_xor_sync(0xffffffffu, rs1, 2);
            Lrow[0] += rs0;
            Lrow[1] += rs1;
        }

        // ---- GEMM2: O += f16(P)·VF ----
        #pragma unroll 1
        for (int kt2 = 0; kt2 < 4; ++kt2){
            uint32_t aP[4];
            aP[0] = packH2(S[2*kt2  ][0], S[2*kt2  ][1]);
            aP[1] = packH2(S[2*kt2  ][2], S[2*kt2  ][3]);
            aP[2] = packH2(S[2*kt2+1][0], S[2*kt2+1][1]);
            aP[3] = packH2(S[2*kt2+1][2], S[2*kt2+1][3]);
            #pragma unroll
            for (int du = 0; du < 4; ++du){
                uint32_t bV[4];
                ldsm4t(sb + OFF_VF
                       + (uint32_t)((16*kt2 + vRow) * QSTRIDE + du*32 + vCh), bV);
                mma16816(O[2*du],   aP, bV[0], bV[1]);
                mma16816(O[2*du+1], aP, bV[2], bV[3]);
            }
        }
    }

    // ---- epilogue: trap flags, normalize, store ----
    int* trapA = (int*)(SM + OFF_TRAP);
    #pragma unroll
    for (int hf = 0; hf < 2; ++hf){
        float l = Lrow[hf];
        if ((lane & 3) == 0){
            int r = 16*w + (lane >> 2) + 8*hf;
            int t = (l == 0.f) ? 1 : 0;
            trapA[r] = t;
            if (t) *(volatile int*)(SM + OFF_FLAG) = 1;
        }
    }

    float* Op = Og + ((size_t)bh * 2048 + (size_t)qb * 128) * 64;
    {
        float inv0 = 1.f / Lrow[0];
        float inv1 = 1.f / Lrow[1];
        int rr0 = 16*w + (lane >> 2);
        int rr1 = rr0 + 8;
        #pragma unroll
        for (int dt = 0; dt < 8; ++dt){
            int c = dt * 8 + 2 * (lane & 3);
            *(float2*)(Op + (size_t)rr0 * 64 + c) =
                make_float2(O[dt][0] * inv0, O[dt][1] * inv0);
            *(float2*)(Op + (size_t)rr1 * 64 + c) =
                make_float2(O[dt][2] * inv1, O[dt][3] * inv1);
        }
    }

    // ---- trap rows: reference collapses to UNIFORM attention over
    //      {k <= q} U {k > q unmasked} (fp32 absorbs s into -1e10 exactly) ----
    __syncthreads();
    if (*(volatile int*)(SM + OFF_FLAG)){
        for (int r = 0; r < 128; ++r){
            if (!trapA[r]) continue;
            int qr = qb * 128 + r;
            if (tid < 64){
                const float* Vb = Vg + (size_t)bh * 2048 * 64;
                const int*   mb = maskg + batch * 2048;
                float acc = 0.f; int cnt = 0;
                for (int k = 0; k < 2048; ++k){
                    bool ok = (k <= qr) || (mb[k] != 0);
                    if (ok){ acc += Vb[(size_t)k * 64 + tid]; cnt++; }
                }
                Og[((size_t)bh * 2048 + qr) * 64 + tid] = acc / (float)cnt;
            }
        }
    }
}

extern "C" void kernel_launch(void* const* d_in, const int* in_sizes, int n_in,
                              void* d_out, int out_size)
{
    const float* Q    = (const float*)d_in[0];
    const float* K    = (const float*)d_in[1];
    const float* V    = (const float*)d_in[2];
    const int*   mask = (const int*)d_in[3];
    float* O = (float*)d_out;

    cudaFuncSetAttribute(attn_mma, cudaFuncAttributeMaxDynamicSharedMemorySize,
                         SMEM_TOTAL);
    dim3 grid(16, 64);
    attn_mma<<<grid, 256, SMEM_TOTAL>>>(Q, K, V, mask, O);
}

// round 16
// speedup vs baseline: 1.3304x; 1.0358x over previous
#include <cuda_runtime.h>
#include <cuda_fp16.h>
#include <stdint.h>

// HMMA fp16 2-pass split-precision flash attention, sm_103 base ISA.
// bs=4, h=16 (bs_h=64), S=2048, d=64. CTA = 128 q-rows, 8 warps x 16 rows.
// 128 keys converted per loop iteration (one barrier pair / two k-tiles):
// fixed latency (LDG exposure + barriers) amortized over 2x the tensor work.
// GEMM1: S = f16(Q/8)·(Khi+Klo); GEMM2: O += f16(P)·(Vhi+Vlo).
// Softmax: p = ex2(S*log2e + C), pad/causal/shift folded into C; masked -> 0.

#define QSTRIDE 144               // f16 tile row pitch bytes (72 halves)

#define OFF_MADD 0                // float[128]: C per key col (128-key phase)
#define OFF_TRAP 768              // int[128]
#define OFF_FLAG 1280             // int
#define OFF_QF   2048             // [128][72] f16
#define OFF_KHI  (OFF_QF  + 128*QSTRIDE)   // [128][72] (two 64-key tiles)
#define OFF_KLO  (OFF_KHI + 128*QSTRIDE)
#define OFF_VHI  (OFF_KLO + 128*QSTRIDE)   // [key][dim]
#define OFF_VLO  (OFF_VHI + 128*QSTRIDE)
#define SMEM_TOTAL (OFF_VLO + 128*QSTRIDE) // 94208 B -> 2 CTAs/SM

#define L2E   1.4426950408889634f
#define SHC   (-11.541560327111707f)   // -8*log2e
#define NEGC  (-1.4426950e10f)         // huge negative -> ex2 == exact 0

// ---------------------------------------------------------------- helpers
__device__ __forceinline__ uint32_t s2u(const void* p){
    uint32_t a;
    asm("{ .reg .u64 t; cvta.to.shared.u64 t, %1; cvt.u32.u64 %0, t; }"
        : "=r"(a) : "l"(p));
    return a;
}
__device__ __forceinline__ void ldsm4(uint32_t a, uint32_t* r){
    asm volatile("ldmatrix.sync.aligned.m8n8.x4.shared.b16 {%0,%1,%2,%3}, [%4];"
        : "=r"(r[0]), "=r"(r[1]), "=r"(r[2]), "=r"(r[3]) : "r"(a));
}
__device__ __forceinline__ void ldsm4t(uint32_t a, uint32_t* r){
    asm volatile("ldmatrix.sync.aligned.m8n8.x4.trans.shared.b16 {%0,%1,%2,%3}, [%4];"
        : "=r"(r[0]), "=r"(r[1]), "=r"(r[2]), "=r"(r[3]) : "r"(a));
}
__device__ __forceinline__ void mma16816(float* c, const uint32_t* a,
                                         uint32_t b0, uint32_t b1){
    asm volatile("mma.sync.aligned.m16n8k16.row.col.f32.f16.f16.f32 "
        "{%0,%1,%2,%3},{%4,%5,%6,%7},{%8,%9},{%0,%1,%2,%3};"
        : "+f"(c[0]), "+f"(c[1]), "+f"(c[2]), "+f"(c[3])
        : "r"(a[0]), "r"(a[1]), "r"(a[2]), "r"(a[3]), "r"(b0), "r"(b1));
}
__device__ __forceinline__ float ex2f(float t){
    float p;
    asm("ex2.approx.f32 %0, %1;" : "=f"(p) : "f"(t));
    return p;
}
__device__ __forceinline__ void splitH2(float a, float b, uint32_t& hw, uint32_t& lw){
    __half2 h = __floats2half2_rn(a, b);
    float2 f = __half22float2(h);
    __half2 l = __floats2half2_rn(a - f.x, b - f.y);
    hw = *(uint32_t*)&h;
    lw = *(uint32_t*)&l;
}
__device__ __forceinline__ uint32_t packH2(float a, float b){
    __half2 h = __floats2half2_rn(a, b);
    return *(uint32_t*)&h;
}

// ------------------------------------------------------------------- kernel
__global__ void __launch_bounds__(256, 2)
attn_mma(const float* __restrict__ Qg, const float* __restrict__ Kg,
         const float* __restrict__ Vg, const int* __restrict__ maskg,
         float* __restrict__ Og)
{
    extern __shared__ char SM[];
    const uint32_t sb = s2u(SM);
    const int tid  = threadIdx.x;
    const int lane = tid & 31;
    const int w    = tid >> 5;                    // warp owns rows 16w..16w+15
    const int bh   = blockIdx.y;
    const int bx   = blockIdx.x;
    const int qb   = (bx == 0) ? 0 : (16 - bx);   // trap-capable qb=0 first
    const int batch = bh & 3;

    if (tid == 0) *(int*)(SM + OFF_FLAG) = 0;

    // ---- convert Q tile (pre-scaled by 1/8) -> fp16 smem ----
    const float* Qp = Qg + ((size_t)bh * 2048 + (size_t)qb * 128) * 64;
    for (int i = tid; i < 2048; i += 256){
        int r = i >> 4, c4 = (i & 15) << 2;
        float4 v = *(const float4*)(Qp + r * 64 + c4);
        uint32_t q0 = packH2(v.x * 0.125f, v.y * 0.125f);
        uint32_t q1 = packH2(v.z * 0.125f, v.w * 0.125f);
        *(uint2*)(SM + OFF_QF + (uint32_t)(r * QSTRIDE + c4 * 2)) = make_uint2(q0, q1);
    }

    float O[8][4];
    float Lrow[2] = {0.f, 0.f};
    #pragma unroll
    for (int n = 0; n < 8; ++n)
        #pragma unroll
        for (int e = 0; e < 4; ++e) O[n][e] = 0.f;

    const int lr16 = lane & 15;
    const int aCh  = (lane >> 4) << 4;
    const int bRow = (lane & 7) + ((lane >> 4) << 3);
    const int bCh  = ((lane >> 3) & 1) << 4;
    const int vRow = (lane & 7) + (((lane >> 3) & 1) << 3);
    const int vCh  = (lane >> 4) << 4;
    const int r01  = qb * 128 + 16 * w + (lane >> 2);
    const int r23  = r01 + 8;

    const int nit = qb + 1;                    // 128-key phases
    for (int j = 0; j < nit; ++j){
        __syncthreads();   // previous phase's smem reads done (covers Q init)
        // ---- convert K,V (128 keys) -> fp16 hi/lo ----
        const float* Kp = Kg + ((size_t)bh * 2048 + (size_t)j * 128) * 64;
        const float* Vp = Vg + ((size_t)bh * 2048 + (size_t)j * 128) * 64;
        for (int i = tid; i < 2048; i += 256){
            int r = i >> 4, c4 = (i & 15) << 2;
            uint32_t off = (uint32_t)(r * QSTRIDE + c4 * 2);
            float4 v = *(const float4*)(Kp + r * 64 + c4);
            uint32_t h0,l0,h1,l1;
            splitH2(v.x, v.y, h0, l0);
            splitH2(v.z, v.w, h1, l1);
            *(uint2*)(SM + OFF_KHI + off) = make_uint2(h0, h1);
            *(uint2*)(SM + OFF_KLO + off) = make_uint2(l0, l1);
            v = *(const float4*)(Vp + r * 64 + c4);
            splitH2(v.x, v.y, h0, l0);
            splitH2(v.z, v.w, h1, l1);
            *(uint2*)(SM + OFF_VHI + off) = make_uint2(h0, h1);
            *(uint2*)(SM + OFF_VLO + off) = make_uint2(l0, l1);
        }
        if (tid < 128)
            ((float*)(SM + OFF_MADD))[tid] =
                maskg[batch * 2048 + j * 128 + tid] ? SHC : NEGC;
        __syncthreads();

        // ---- two 64-key halves: GEMM1 -> softmax -> GEMM2 (no barriers) ----
        #pragma unroll 1
        for (int h = 0; h < 2; ++h){
            const int rowb = 64 * h;               // key-row base in smem bufs
            const int kgb  = j * 128 + 64 * h;     // global key base

            // GEMM1: S = QF·Khi^T + QF·Klo^T
            float S[8][4];
            #pragma unroll
            for (int n = 0; n < 8; ++n)
                #pragma unroll
                for (int e = 0; e < 4; ++e) S[n][e] = 0.f;

            #pragma unroll 1
            for (int kt = 0; kt < 4; ++kt){
                uint32_t aF[4];
                ldsm4(sb + OFF_QF
                      + (uint32_t)((16*w + lr16) * QSTRIDE + kt*32 + aCh), aF);
                #pragma unroll
                for (int u = 0; u < 4; ++u){
                    uint32_t bH[4], bL[4];
                    uint32_t ad = sb + OFF_KHI
                        + (uint32_t)((rowb + 16*u + bRow) * QSTRIDE + kt*32 + bCh);
                    ldsm4(ad, bH);
                    ldsm4(ad + (OFF_KLO - OFF_KHI), bL);
                    mma16816(S[2*u],   aF, bH[0], bH[1]);
                    mma16816(S[2*u],   aF, bL[0], bL[1]);
                    mma16816(S[2*u+1], aF, bH[2], bH[3]);
                    mma16816(S[2*u+1], aF, bL[2], bL[3]);
                }
            }

            // softmax: p = ex2(S*log2e + C); masked -> exact 0
            const float* mAddp = (const float*)(SM + OFF_MADD) + 64 * h;
            {
                float rs0 = 0.f, rs1 = 0.f;
                #pragma unroll
                for (int n = 0; n < 8; ++n){
                    int c0 = n * 8 + 2 * (lane & 3);
                    int kg = kgb + c0;
                    float pad0 = mAddp[c0], pad1 = mAddp[c0 + 1];
                    float p0 = ex2f(fmaf(S[n][0], L2E, (kg     > r01) ? NEGC : pad0));
                    float p1 = ex2f(fmaf(S[n][1], L2E, (kg + 1 > r01) ? NEGC : pad1));
                    float p2 = ex2f(fmaf(S[n][2], L2E, (kg     > r23) ? NEGC : pad0));
                    float p3 = ex2f(fmaf(S[n][3], L2E, (kg + 1 > r23) ? NEGC : pad1));
                    S[n][0] = p0; S[n][1] = p1;
                    S[n][2] = p2; S[n][3] = p3;
                    rs0 += p0 + p1;
                    rs1 += p2 + p3;
                }
                rs0 += __shfl_xor_sync(0xffffffffu, rs0, 1);
                rs0 += __shfl_xor_sync(0xffffffffu, rs0, 2);
                rs1 += __shfl_xor_sync(0xffffffffu, rs1, 1);
                rs1 += __shfl_xor_sync(0xffffffffu, rs1, 2);
                Lrow[0] += rs0;
                Lrow[1] += rs1;
            }

            // GEMM2: O += f16(P)·Vhi + f16(P)·Vlo
            #pragma unroll 1
            for (int kt2 = 0; kt2 < 4; ++kt2){
                uint32_t aP[4];
                aP[0] = packH2(S[2*kt2  ][0], S[2*kt2  ][1]);
                aP[1] = packH2(S[2*kt2  ][2], S[2*kt2  ][3]);
                aP[2] = packH2(S[2*kt2+1][0], S[2*kt2+1][1]);
                aP[3] = packH2(S[2*kt2+1][2], S[2*kt2+1][3]);
                #pragma unroll
                for (int du = 0; du < 4; ++du){
                    uint32_t bVh[4], bVl[4];
                    uint32_t ad = sb + OFF_VHI
                        + (uint32_t)((rowb + 16*kt2 + vRow) * QSTRIDE + du*32 + vCh);
                    ldsm4t(ad, bVh);
                    ldsm4t(ad + (OFF_VLO - OFF_VHI), bVl);
                    mma16816(O[2*du],   aP, bVh[0], bVh[1]);
                    mma16816(O[2*du],   aP, bVl[0], bVl[1]);
                    mma16816(O[2*du+1], aP, bVh[2], bVh[3]);
                    mma16816(O[2*du+1], aP, bVl[2], bVl[3]);
                }
            }
        }
    }

    // ---- epilogue: trap flags, normalize, store ----
    int* trapA = (int*)(SM + OFF_TRAP);
    #pragma unroll
    for (int hf = 0; hf < 2; ++hf){
        float l = Lrow[hf];
        if ((lane & 3) == 0){
            int r = 16*w + (lane >> 2) + 8*hf;
            int t = (l == 0.f) ? 1 : 0;
            trapA[r] = t;
            if (t) *(volatile int*)(SM + OFF_FLAG) = 1;
        }
    }

    float* Op = Og + ((size_t)bh * 2048 + (size_t)qb * 128) * 64;
    {
        float inv0 = 1.f / Lrow[0];
        float inv1 = 1.f / Lrow[1];
        int rr0 = 16*w + (lane >> 2);
        int rr1 = rr0 + 8;
        #pragma unroll
        for (int dt = 0; dt < 8; ++dt){
            int c = dt * 8 + 2 * (lane & 3);
            *(float2*)(Op + (size_t)rr0 * 64 + c) =
                make_float2(O[dt][0] * inv0, O[dt][1] * inv0);
            *(float2*)(Op + (size_t)rr1 * 64 + c) =
                make_float2(O[dt][2] * inv1, O[dt][3] * inv1);
        }
    }

    // ---- trap rows: reference collapses to UNIFORM attention over
    //      {k <= q} U {k > q unmasked} (fp32 absorbs s into -1e10 exactly) ----
    __syncthreads();
    if (*(volatile int*)(SM + OFF_FLAG)){
        for (int r = 0; r < 128; ++r){
            if (!trapA[r]) continue;
            int qr = qb * 128 + r;
            if (tid < 64){
                const float* Vb = Vg + (size_t)bh * 2048 * 64;
                const int*   mb = maskg + batch * 2048;
                float acc = 0.f; int cnt = 0;
                for (int k = 0; k < 2048; ++k){
                    bool ok = (k <= qr) || (mb[k] != 0);
                    if (ok){ acc += Vb[(size_t)k * 64 + tid]; cnt++; }
                }
                Og[((size_t)bh * 2048 + qr) * 64 + tid] = acc / (float)cnt;
            }
        }
    }
}

extern "C" void kernel_launch(void* const* d_in, const int* in_sizes, int n_in,
                              void* d_out, int out_size)
{
    const float* Q    = (const float*)d_in[0];
    const float* K    = (const float*)d_in[1];
    const float* V    = (const float*)d_in[2];
    const int*   mask = (const int*)d_in[3];
    float* O = (float*)d_out;

    cudaFuncSetAttribute(attn_mma, cudaFuncAttributeMaxDynamicSharedMemorySize,
                         SMEM_TOTAL);
    dim3 grid(16, 64);
    attn_mma<<<grid, 256, SMEM_TOTAL>>>(Q, K, V, mask, O);
}